// round 1
// baseline (speedup 1.0000x reference)
#include <cuda_runtime.h>
#include <math.h>

// Problem shape (fixed by the dataset):
//   x:(4,2048,1024) f32, pad:(4,2048) i32, wq/wk/wv/wo:(1024,1024) f32,
//   bq/bk/bv/bo:(1024) f32, h_num=16 (depth=64). out:(4,2048,1024) f32.
static const int Bb = 4;
static const int Nn = 2048;
static const int Dd = 1024;
static const int Hh = 16;
static const int DEP = 64;
static const int Mm = Bb * Nn; // 8192

// Scratch (allocation-free per harness rules): Q,K,V post-projection and
// attention output O, all in (B*N, D) row-major layout. Head h occupies
// columns [h*64, h*64+64) — identical to the reference's head-split view.
__device__ float g_Q[8192 * 1024];
__device__ float g_K[8192 * 1024];
__device__ float g_V[8192 * 1024];
__device__ float g_O[8192 * 1024];

// ---------------------------------------------------------------------------
// SGEMM with bias: C[M,N] = A[M,K] @ W[K,N] + bias[N]
// 128x128 block tile, BK=8, 256 threads, 8x8 register tile per thread.
// ---------------------------------------------------------------------------
__global__ __launch_bounds__(256) void sgemm_bias_kernel(
    const float* __restrict__ A, const float* __restrict__ W,
    const float* __restrict__ bias, float* __restrict__ C,
    int M, int N, int K)
{
    const int BM = 128, BN = 128, BK = 8;
    __shared__ float As[BK][BM];
    __shared__ float Bs[BK][BN];

    int tid  = threadIdx.x;
    int brow = blockIdx.y * BM;
    int bcol = blockIdx.x * BN;

    // A tile load map: 128 rows x 8 cols = 1024 floats = 256 x float4
    int arow = tid >> 1;           // 0..127
    int acol = (tid & 1) * 4;      // 0 or 4
    // B tile load map: 8 rows x 128 cols
    int brl = tid >> 5;            // 0..7
    int bcl = (tid & 31) * 4;      // 0..124

    int ty = tid >> 4;             // 0..15 (row group)
    int tx = tid & 15;             // 0..15 (col group)

    float acc[8][8];
#pragma unroll
    for (int i = 0; i < 8; i++)
#pragma unroll
        for (int j = 0; j < 8; j++) acc[i][j] = 0.0f;

    const float* Ap = A + (size_t)brow * K;
    const float* Wp = W + bcol;

    for (int k0 = 0; k0 < K; k0 += BK) {
        float4 a4 = *(const float4*)(Ap + (size_t)arow * K + k0 + acol);
        As[acol + 0][arow] = a4.x;
        As[acol + 1][arow] = a4.y;
        As[acol + 2][arow] = a4.z;
        As[acol + 3][arow] = a4.w;
        *(float4*)(&Bs[brl][bcl]) =
            *(const float4*)(Wp + (size_t)(k0 + brl) * N + bcl);
        __syncthreads();

#pragma unroll
        for (int kk = 0; kk < BK; kk++) {
            float ar[8], br[8];
#pragma unroll
            for (int i = 0; i < 8; i++) ar[i] = As[kk][ty * 8 + i];
#pragma unroll
            for (int j = 0; j < 8; j++) br[j] = Bs[kk][tx * 8 + j];
#pragma unroll
            for (int i = 0; i < 8; i++)
#pragma unroll
                for (int j = 0; j < 8; j++)
                    acc[i][j] = fmaf(ar[i], br[j], acc[i][j]);
        }
        __syncthreads();
    }

#pragma unroll
    for (int i = 0; i < 8; i++) {
        int r = brow + ty * 8 + i;
#pragma unroll
        for (int j = 0; j < 8; j += 4) {
            int c = bcol + tx * 8 + j;
            float4 v;
            v.x = acc[i][j + 0] + bias[c + 0];
            v.y = acc[i][j + 1] + bias[c + 1];
            v.z = acc[i][j + 2] + bias[c + 2];
            v.w = acc[i][j + 3] + bias[c + 3];
            *(float4*)(C + (size_t)r * N + c) = v;
        }
    }
}

// ---------------------------------------------------------------------------
// Flash-style attention, fp32. One block = 128 query rows of one (b,h).
// One thread owns one query row: q[64] and o[64] in registers.
// Keys processed in SMEM tiles of 64 (K and V), online softmax in chunks
// of 16 keys.
// Masking replicates the reference EXACTLY: s += (1 - vn*vm) * (-1e6).
// (A fully padded query row gets a uniform -1e6 shift, which cancels in
// softmax — so no hard -inf masking.)
// ---------------------------------------------------------------------------
__global__ __launch_bounds__(128) void attn_kernel(
    const float* __restrict__ Q, const float* __restrict__ K,
    const float* __restrict__ V, const int* __restrict__ pad,
    float* __restrict__ O)
{
    __shared__ float Ks[64][64];
    __shared__ float Vs[64][64];
    __shared__ float vsm[64];

    int tid = threadIdx.x;
    int bh  = blockIdx.y;
    int b   = bh >> 4;        // /16
    int h   = bh & 15;
    int n   = blockIdx.x * 128 + tid;   // query row within sequence

    const size_t rowQ = ((size_t)b * Nn + n) * Dd + h * DEP;

    float q[64];
#pragma unroll
    for (int d = 0; d < 64; d += 4) {
        float4 t = *(const float4*)(Q + rowQ + d);
        q[d + 0] = t.x * 0.125f;   // 1/sqrt(depth=64)
        q[d + 1] = t.y * 0.125f;
        q[d + 2] = t.z * 0.125f;
        q[d + 3] = t.w * 0.125f;
    }
    float vn = (pad[b * Nn + n] == 0) ? 1.0f : 0.0f;

    float o[64];
#pragma unroll
    for (int d = 0; d < 64; d++) o[d] = 0.0f;
    float mrun = -1e30f;
    float lrun = 0.0f;

    for (int kt = 0; kt < Nn; kt += 64) {
        __syncthreads();  // protect previous tile's reads
        // cooperative coalesced load of K/V tiles (64x64 each)
        for (int idx = tid; idx < 64 * 16; idx += 128) {
            int mm = idx >> 4;       // 0..63
            int d4 = idx & 15;       // 0..15 (float4 index)
            size_t g = ((size_t)b * Nn + kt + mm) * Dd + h * DEP + d4 * 4;
            *(float4*)(&Ks[mm][d4 * 4]) = *(const float4*)(K + g);
            *(float4*)(&Vs[mm][d4 * 4]) = *(const float4*)(V + g);
        }
        if (tid < 64)
            vsm[tid] = (pad[b * Nn + kt + tid] == 0) ? 1.0f : 0.0f;
        __syncthreads();

#pragma unroll 1
        for (int mt = 0; mt < 64; mt += 16) {
            float sbuf[16];
            float tmax = -1e30f;
#pragma unroll
            for (int j = 0; j < 16; j++) {
                const float4* kp = (const float4*)Ks[mt + j];
                float s0 = 0.f, s1 = 0.f, s2 = 0.f, s3 = 0.f;
#pragma unroll
                for (int d4 = 0; d4 < 16; d4++) {
                    float4 kv = kp[d4];
                    s0 = fmaf(q[d4 * 4 + 0], kv.x, s0);
                    s1 = fmaf(q[d4 * 4 + 1], kv.y, s1);
                    s2 = fmaf(q[d4 * 4 + 2], kv.z, s2);
                    s3 = fmaf(q[d4 * 4 + 3], kv.w, s3);
                }
                float s = (s0 + s1) + (s2 + s3);
                s += (1.0f - vn * vsm[mt + j]) * (-1e6f);
                sbuf[j] = s;
                tmax = fmaxf(tmax, s);
            }
            float mnew  = fmaxf(mrun, tmax);
            float alpha = __expf(mrun - mnew);
            mrun = mnew;
            lrun *= alpha;
#pragma unroll
            for (int d = 0; d < 64; d++) o[d] *= alpha;
#pragma unroll
            for (int j = 0; j < 16; j++) {
                float p = __expf(sbuf[j] - mnew);
                lrun += p;
                const float4* vp = (const float4*)Vs[mt + j];
#pragma unroll
                for (int d4 = 0; d4 < 16; d4++) {
                    float4 vv = vp[d4];
                    o[d4 * 4 + 0] = fmaf(p, vv.x, o[d4 * 4 + 0]);
                    o[d4 * 4 + 1] = fmaf(p, vv.y, o[d4 * 4 + 1]);
                    o[d4 * 4 + 2] = fmaf(p, vv.z, o[d4 * 4 + 2]);
                    o[d4 * 4 + 3] = fmaf(p, vv.w, o[d4 * 4 + 3]);
                }
            }
        }
    }

    float inv = 1.0f / lrun;
#pragma unroll
    for (int d = 0; d < 64; d += 4) {
        float4 t;
        t.x = o[d + 0] * inv;
        t.y = o[d + 1] * inv;
        t.z = o[d + 2] * inv;
        t.w = o[d + 3] * inv;
        *(float4*)(O + rowQ + d) = t;
    }
}

// ---------------------------------------------------------------------------
// Launch
// ---------------------------------------------------------------------------
extern "C" void kernel_launch(void* const* d_in, const int* in_sizes, int n_in,
                              void* d_out, int out_size)
{
    const float* x  = (const float*)d_in[0];
    const int*   pd = (const int*)d_in[1];
    const float* wq = (const float*)d_in[2];
    const float* bq = (const float*)d_in[3];
    const float* wk = (const float*)d_in[4];
    const float* bk = (const float*)d_in[5];
    const float* wv = (const float*)d_in[6];
    const float* bv = (const float*)d_in[7];
    const float* wo = (const float*)d_in[8];
    const float* bo = (const float*)d_in[9];
    float* out = (float*)d_out;

    float *Q, *K, *V, *O;
    cudaGetSymbolAddress((void**)&Q, g_Q);
    cudaGetSymbolAddress((void**)&K, g_K);
    cudaGetSymbolAddress((void**)&V, g_V);
    cudaGetSymbolAddress((void**)&O, g_O);

    dim3 ggrid(Dd / 128, Mm / 128);   // (8, 64)
    sgemm_bias_kernel<<<ggrid, 256>>>(x, wq, bq, Q, Mm, Dd, Dd);
    sgemm_bias_kernel<<<ggrid, 256>>>(x, wk, bk, K, Mm, Dd, Dd);
    sgemm_bias_kernel<<<ggrid, 256>>>(x, wv, bv, V, Mm, Dd, Dd);

    dim3 agrid(Nn / 128, Bb * Hh);    // (16, 64)
    attn_kernel<<<agrid, 128>>>(Q, K, V, pd, O);

    sgemm_bias_kernel<<<ggrid, 256>>>(O, wo, bo, out, Mm, Dd, Dd);
}

// round 4
// speedup vs baseline: 1.2524x; 1.2524x over previous
#include <cuda_runtime.h>
#include <cuda_bf16.h>
#include <cstdint>
#include <math.h>

// Shapes fixed by dataset: x:(4,2048,1024) f32, pad:(4,2048) i32,
// w*:(1024,1024) f32, b*:(1024) f32, h=16 (depth 64). out:(4,2048,1024) f32.
static const int Bb = 4;
static const int Nn = 2048;
static const int Dd = 1024;
static const int DEP = 64;
static const int Mm = Bb * Nn; // 8192

// Scratch (no allocs allowed).
__device__ float g_Q[8192 * 1024];
__device__ float g_K[8192 * 1024];
__device__ float g_V[8192 * 1024];
__device__ float g_O[8192 * 1024];
__device__ float g_WT[4 * 1024 * 1024];

// ---------------------------------------------------------------------------
// Helpers (sm_80-era PTX only: mma.sync + ldmatrix; NO tcgen05)
// ---------------------------------------------------------------------------
__device__ __forceinline__ uint32_t smem_u32(const void* p) {
    uint32_t a;
    asm("{ .reg .u64 t; cvta.to.shared.u64 t, %1; cvt.u32.u64 %0, t; }"
        : "=r"(a) : "l"(p));
    return a;
}
__device__ __forceinline__ void ldm4(uint32_t* q, uint32_t addr) {
    asm volatile("ldmatrix.sync.aligned.m8n8.x4.shared.b16 {%0,%1,%2,%3}, [%4];"
                 : "=r"(q[0]), "=r"(q[1]), "=r"(q[2]), "=r"(q[3]) : "r"(addr));
}
__device__ __forceinline__ void mma_bf16(float* c, const uint32_t* a,
                                         uint32_t b0, uint32_t b1) {
    asm volatile(
        "mma.sync.aligned.m16n8k16.row.col.f32.bf16.bf16.f32 "
        "{%0,%1,%2,%3}, {%4,%5,%6,%7}, {%8,%9}, {%0,%1,%2,%3};"
        : "+f"(c[0]), "+f"(c[1]), "+f"(c[2]), "+f"(c[3])
        : "r"(a[0]), "r"(a[1]), "r"(a[2]), "r"(a[3]), "r"(b0), "r"(b1));
}
__device__ __forceinline__ uint32_t pack2(__nv_bfloat16 a, __nv_bfloat16 b) {
    __nv_bfloat162 t;
    t.x = a; t.y = b;
    return *reinterpret_cast<uint32_t*>(&t);
}

// ---------------------------------------------------------------------------
// 1024x1024 transpose: WT[n][k] = W[k][n]
// ---------------------------------------------------------------------------
__global__ __launch_bounds__(256) void transpose_k(
    const float* __restrict__ in, float* __restrict__ out)
{
    __shared__ float t[32][33];
    int x = blockIdx.x * 32 + threadIdx.x;
    int y = blockIdx.y * 32 + threadIdx.y;
#pragma unroll
    for (int j = 0; j < 32; j += 8)
        t[threadIdx.y + j][threadIdx.x] = in[(size_t)(y + j) * 1024 + x];
    __syncthreads();
    int xo = blockIdx.y * 32 + threadIdx.x;
    int yo = blockIdx.x * 32 + threadIdx.y;
#pragma unroll
    for (int j = 0; j < 32; j += 8)
        out[(size_t)(yo + j) * 1024 + xo] = t[threadIdx.x][threadIdx.y + j];
}

// ---------------------------------------------------------------------------
// bf16x3 GEMM via mma.sync: C[M,1024] = A[M,1024] @ W + bias, with
// BT[n][k] = W[k][n] as the B operand (row.col mma wants exactly this).
//
// Block: 128x128 C tile, 256 threads (8 warps, 4x2 warp grid, 32x64/warp).
// K chunk = 32, stored as 4 k8-panels per split: panel[g][row][8 halves],
// row stride 16B (conflict-free ldmatrix), panel stride 2080B (pad).
// hi/lo bf16 splits; 3 mma products (hh, hl, lh) into fp32 accumulators.
// Double-buffered SMEM + register prefetch. No spin loops.
// ---------------------------------------------------------------------------
static const int PANEL = 2080;               // 128*16 + 32 pad
static const int AHI = 0;
static const int ALO = 4 * PANEL;            // 8320
static const int BHI = 8 * PANEL;            // 16640
static const int BLO = 12 * PANEL;           // 24960
static const int BUFSZ = 16 * PANEL;         // 33280
static const int GEMM_SMEM = 2 * BUFSZ;      // 66560

__global__ __launch_bounds__(256) void gemm_bf16x3_kernel(
    const float* __restrict__ A, const float* __restrict__ BT,
    const float* __restrict__ bias, float* __restrict__ C)
{
    extern __shared__ __align__(16) char smem[];
    const uint32_t sbase = smem_u32(smem);
    const int tid = threadIdx.x;
    const int wid = tid >> 5;
    const int lane = tid & 31;
    const int wm = (wid >> 1) * 32;   // warp M offset in tile
    const int wn = (wid & 1) * 64;    // warp N offset in tile
    const int brow = blockIdx.y * 128;
    const int bcol = blockIdx.x * 128;

    const float* Ap = A + (size_t)brow * 1024;
    const float* Bp = BT + (size_t)bcol * 1024;

    float c[2][8][4];
#pragma unroll
    for (int mt = 0; mt < 2; ++mt)
#pragma unroll
        for (int nt = 0; nt < 8; ++nt)
#pragma unroll
            for (int i = 0; i < 4; ++i) c[mt][nt][i] = 0.0f;

    // ---- global load (coalesced): id = tid + i*256; row=id>>3, f4=id&7 ----
    float4 ra[4], rb[4];
    auto load_chunk = [&](int kbase) {
#pragma unroll
        for (int i = 0; i < 4; ++i) {
            int id = tid + i * 256;
            int row = id >> 3, f4 = id & 7;
            ra[i] = *(const float4*)(Ap + (size_t)row * 1024 + kbase + f4 * 4);
            rb[i] = *(const float4*)(Bp + (size_t)row * 1024 + kbase + f4 * 4);
        }
    };
    auto store_chunk = [&](int buf) {
        char* bp = smem + buf * BUFSZ;
#pragma unroll
        for (int i = 0; i < 4; ++i) {
            int id = tid + i * 256;
            int row = id >> 3, f4 = id & 7;
            int g = f4 >> 1, half = f4 & 1;
            int off = g * PANEL + row * 16 + half * 8;

            float4 v = ra[i];
            __nv_bfloat16 hx = __float2bfloat16_rn(v.x);
            __nv_bfloat16 hy = __float2bfloat16_rn(v.y);
            __nv_bfloat16 hz = __float2bfloat16_rn(v.z);
            __nv_bfloat16 hw = __float2bfloat16_rn(v.w);
            uint2 hi = make_uint2(pack2(hx, hy), pack2(hz, hw));
            uint2 lo = make_uint2(
                pack2(__float2bfloat16_rn(v.x - __bfloat162float(hx)),
                      __float2bfloat16_rn(v.y - __bfloat162float(hy))),
                pack2(__float2bfloat16_rn(v.z - __bfloat162float(hz)),
                      __float2bfloat16_rn(v.w - __bfloat162float(hw))));
            *(uint2*)(bp + AHI + off) = hi;
            *(uint2*)(bp + ALO + off) = lo;

            v = rb[i];
            hx = __float2bfloat16_rn(v.x);
            hy = __float2bfloat16_rn(v.y);
            hz = __float2bfloat16_rn(v.z);
            hw = __float2bfloat16_rn(v.w);
            hi = make_uint2(pack2(hx, hy), pack2(hz, hw));
            lo = make_uint2(
                pack2(__float2bfloat16_rn(v.x - __bfloat162float(hx)),
                      __float2bfloat16_rn(v.y - __bfloat162float(hy))),
                pack2(__float2bfloat16_rn(v.z - __bfloat162float(hz)),
                      __float2bfloat16_rn(v.w - __bfloat162float(hw))));
            *(uint2*)(bp + BHI + off) = hi;
            *(uint2*)(bp + BLO + off) = lo;
        }
    };

    load_chunk(0);
    store_chunk(0);
    __syncthreads();

    for (int ch = 0; ch < 32; ++ch) {
        const int buf = ch & 1;
        if (ch + 1 < 32) load_chunk((ch + 1) * 32);

        const uint32_t bb = sbase + buf * BUFSZ;
#pragma unroll
        for (int ks = 0; ks < 2; ++ks) {
            const int g0 = ks * 2;
            uint32_t Af[2][2][4];      // [split][g-half][quad]
            uint32_t Bf[2][2][2][4];   // [split][g-half][ngrp][quad]
#pragma unroll
            for (int s = 0; s < 2; ++s) {
                const uint32_t aoff = bb + (s ? ALO : AHI);
                const uint32_t boff = bb + (s ? BLO : BHI);
#pragma unroll
                for (int gg = 0; gg < 2; ++gg) {
                    ldm4(Af[s][gg],
                         aoff + (g0 + gg) * PANEL + (wm + lane) * 16);
#pragma unroll
                    for (int ng = 0; ng < 2; ++ng)
                        ldm4(Bf[s][gg][ng],
                             boff + (g0 + gg) * PANEL + (wn + ng * 32 + lane) * 16);
                }
            }
#pragma unroll
            for (int mt = 0; mt < 2; ++mt) {
                uint32_t ah[4] = {Af[0][0][mt * 2], Af[0][0][mt * 2 + 1],
                                  Af[0][1][mt * 2], Af[0][1][mt * 2 + 1]};
                uint32_t al[4] = {Af[1][0][mt * 2], Af[1][0][mt * 2 + 1],
                                  Af[1][1][mt * 2], Af[1][1][mt * 2 + 1]};
#pragma unroll
                for (int nt = 0; nt < 8; ++nt) {
                    const int ng = nt >> 2, q = nt & 3;
                    uint32_t bh0 = Bf[0][0][ng][q], bh1 = Bf[0][1][ng][q];
                    uint32_t bl0 = Bf[1][0][ng][q], bl1 = Bf[1][1][ng][q];
                    mma_bf16(c[mt][nt], ah, bh0, bh1);
                    mma_bf16(c[mt][nt], ah, bl0, bl1);
                    mma_bf16(c[mt][nt], al, bh0, bh1);
                }
            }
        }
        __syncthreads();
        if (ch + 1 < 32) {
            store_chunk(buf ^ 1);
            __syncthreads();
        }
    }

    // ---- epilogue: c frag (r=lane/4 [+8], col=2*(lane%4) [+1]) + bias ----
    const int r0b = brow + wm + (lane >> 2);
    const int colb = bcol + wn + 2 * (lane & 3);
#pragma unroll
    for (int mt = 0; mt < 2; ++mt) {
#pragma unroll
        for (int nt = 0; nt < 8; ++nt) {
            const int col = colb + nt * 8;
            const float2 bi = *(const float2*)(bias + col);
            const int r0 = r0b + mt * 16;
            float2 v0 = make_float2(c[mt][nt][0] + bi.x, c[mt][nt][1] + bi.y);
            float2 v1 = make_float2(c[mt][nt][2] + bi.x, c[mt][nt][3] + bi.y);
            *(float2*)(C + (size_t)r0 * 1024 + col) = v0;
            *(float2*)(C + (size_t)(r0 + 8) * 1024 + col) = v1;
        }
    }
}

// ---------------------------------------------------------------------------
// Flash-style attention, fp32 (unchanged, known-good from R0).
// ---------------------------------------------------------------------------
__global__ __launch_bounds__(128) void attn_kernel(
    const float* __restrict__ Q, const float* __restrict__ K,
    const float* __restrict__ V, const int* __restrict__ pad,
    float* __restrict__ O)
{
    __shared__ float Ks[64][64];
    __shared__ float Vs[64][64];
    __shared__ float vsm[64];

    int tid = threadIdx.x;
    int bh  = blockIdx.y;
    int b   = bh >> 4;
    int h   = bh & 15;
    int n   = blockIdx.x * 128 + tid;

    const size_t rowQ = ((size_t)b * Nn + n) * Dd + h * DEP;

    float q[64];
#pragma unroll
    for (int d = 0; d < 64; d += 4) {
        float4 t = *(const float4*)(Q + rowQ + d);
        q[d + 0] = t.x * 0.125f;
        q[d + 1] = t.y * 0.125f;
        q[d + 2] = t.z * 0.125f;
        q[d + 3] = t.w * 0.125f;
    }
    float vn = (pad[b * Nn + n] == 0) ? 1.0f : 0.0f;

    float o[64];
#pragma unroll
    for (int d = 0; d < 64; d++) o[d] = 0.0f;
    float mrun = -1e30f;
    float lrun = 0.0f;

    for (int kt = 0; kt < Nn; kt += 64) {
        __syncthreads();
        for (int idx = tid; idx < 64 * 16; idx += 128) {
            int mm = idx >> 4;
            int d4 = idx & 15;
            size_t g = ((size_t)b * Nn + kt + mm) * Dd + h * DEP + d4 * 4;
            *(float4*)(&Ks[mm][d4 * 4]) = *(const float4*)(K + g);
            *(float4*)(&Vs[mm][d4 * 4]) = *(const float4*)(V + g);
        }
        if (tid < 64)
            vsm[tid] = (pad[b * Nn + kt + tid] == 0) ? 1.0f : 0.0f;
        __syncthreads();

#pragma unroll 1
        for (int mt = 0; mt < 64; mt += 16) {
            float sbuf[16];
            float tmax = -1e30f;
#pragma unroll
            for (int j = 0; j < 16; j++) {
                const float4* kp = (const float4*)Ks[mt + j];
                float s0 = 0.f, s1 = 0.f, s2 = 0.f, s3 = 0.f;
#pragma unroll
                for (int d4 = 0; d4 < 16; d4++) {
                    float4 kv = kp[d4];
                    s0 = fmaf(q[d4 * 4 + 0], kv.x, s0);
                    s1 = fmaf(q[d4 * 4 + 1], kv.y, s1);
                    s2 = fmaf(q[d4 * 4 + 2], kv.z, s2);
                    s3 = fmaf(q[d4 * 4 + 3], kv.w, s3);
                }
                float s = (s0 + s1) + (s2 + s3);
                s += (1.0f - vn * vsm[mt + j]) * (-1e6f);
                sbuf[j] = s;
                tmax = fmaxf(tmax, s);
            }
            float mnew  = fmaxf(mrun, tmax);
            float alpha = __expf(mrun - mnew);
            mrun = mnew;
            lrun *= alpha;
#pragma unroll
            for (int d = 0; d < 64; d++) o[d] *= alpha;
#pragma unroll
            for (int j = 0; j < 16; j++) {
                float p = __expf(sbuf[j] - mnew);
                lrun += p;
                const float4* vp = (const float4*)Vs[mt + j];
#pragma unroll
                for (int d4 = 0; d4 < 16; d4++) {
                    float4 vv = vp[d4];
                    o[d4 * 4 + 0] = fmaf(p, vv.x, o[d4 * 4 + 0]);
                    o[d4 * 4 + 1] = fmaf(p, vv.y, o[d4 * 4 + 1]);
                    o[d4 * 4 + 2] = fmaf(p, vv.z, o[d4 * 4 + 2]);
                    o[d4 * 4 + 3] = fmaf(p, vv.w, o[d4 * 4 + 3]);
                }
            }
        }
    }

    float inv = 1.0f / lrun;
#pragma unroll
    for (int d = 0; d < 64; d += 4) {
        float4 t;
        t.x = o[d + 0] * inv;
        t.y = o[d + 1] * inv;
        t.z = o[d + 2] * inv;
        t.w = o[d + 3] * inv;
        *(float4*)(O + rowQ + d) = t;
    }
}

// ---------------------------------------------------------------------------
// Launch
// ---------------------------------------------------------------------------
extern "C" void kernel_launch(void* const* d_in, const int* in_sizes, int n_in,
                              void* d_out, int out_size)
{
    const float* x  = (const float*)d_in[0];
    const int*   pd = (const int*)d_in[1];
    const float* wq = (const float*)d_in[2];
    const float* bq = (const float*)d_in[3];
    const float* wk = (const float*)d_in[4];
    const float* bk = (const float*)d_in[5];
    const float* wv = (const float*)d_in[6];
    const float* bv = (const float*)d_in[7];
    const float* wo = (const float*)d_in[8];
    const float* bo = (const float*)d_in[9];
    float* out = (float*)d_out;

    float *Q, *K, *V, *O, *WT;
    cudaGetSymbolAddress((void**)&Q, g_Q);
    cudaGetSymbolAddress((void**)&K, g_K);
    cudaGetSymbolAddress((void**)&V, g_V);
    cudaGetSymbolAddress((void**)&O, g_O);
    cudaGetSymbolAddress((void**)&WT, g_WT);

    cudaFuncSetAttribute(gemm_bf16x3_kernel,
                         cudaFuncAttributeMaxDynamicSharedMemorySize, GEMM_SMEM);

    dim3 tgrid(32, 32), tblk(32, 8);
    transpose_k<<<tgrid, tblk>>>(wq, WT + 0 * 1024 * 1024);
    transpose_k<<<tgrid, tblk>>>(wk, WT + 1 * 1024 * 1024);
    transpose_k<<<tgrid, tblk>>>(wv, WT + 2 * 1024 * 1024);
    transpose_k<<<tgrid, tblk>>>(wo, WT + 3 * 1024 * 1024);

    dim3 ggrid(Dd / 128, Mm / 128); // (8, 64)
    gemm_bf16x3_kernel<<<ggrid, 256, GEMM_SMEM>>>(x, WT + 0 * 1024 * 1024, bq, Q);
    gemm_bf16x3_kernel<<<ggrid, 256, GEMM_SMEM>>>(x, WT + 1 * 1024 * 1024, bk, K);
    gemm_bf16x3_kernel<<<ggrid, 256, GEMM_SMEM>>>(x, WT + 2 * 1024 * 1024, bv, V);

    dim3 agrid(Nn / 128, Bb * 16); // (16, 64)
    attn_kernel<<<agrid, 128>>>(Q, K, V, pd, O);

    gemm_bf16x3_kernel<<<ggrid, 256, GEMM_SMEM>>>(O, WT + 3 * 1024 * 1024, bo, out);
}

// round 7
// speedup vs baseline: 2.4857x; 1.9846x over previous
#include <cuda_runtime.h>
#include <cuda_bf16.h>
#include <cstdint>
#include <math.h>

// Shapes fixed by dataset: x:(4,2048,1024) f32, pad:(4,2048) i32,
// w*:(1024,1024) f32, b*:(1024) f32, h=16 (depth 64). out:(4,2048,1024) f32.
static const int Bb = 4;
static const int Nn = 2048;
static const int Dd = 1024;
static const int Mm = Bb * Nn; // 8192

// Scratch (no allocs allowed).
__device__ float g_Q[8192 * 1024];
__device__ float g_K[8192 * 1024];
__device__ float g_V[8192 * 1024];
__device__ float g_O[8192 * 1024];
__device__ float g_WT[4 * 1024 * 1024];

// ---------------------------------------------------------------------------
// Helpers (sm_80-era PTX only: mma.sync + ldmatrix; NO tcgen05)
// ---------------------------------------------------------------------------
__device__ __forceinline__ uint32_t smem_u32(const void* p) {
    uint32_t a;
    asm("{ .reg .u64 t; cvta.to.shared.u64 t, %1; cvt.u32.u64 %0, t; }"
        : "=r"(a) : "l"(p));
    return a;
}
__device__ __forceinline__ void ldm4(uint32_t* q, uint32_t addr) {
    asm volatile("ldmatrix.sync.aligned.m8n8.x4.shared.b16 {%0,%1,%2,%3}, [%4];"
                 : "=r"(q[0]), "=r"(q[1]), "=r"(q[2]), "=r"(q[3]) : "r"(addr));
}
__device__ __forceinline__ void ldm4t(uint32_t* q, uint32_t addr) {
    asm volatile("ldmatrix.sync.aligned.m8n8.x4.trans.shared.b16 {%0,%1,%2,%3}, [%4];"
                 : "=r"(q[0]), "=r"(q[1]), "=r"(q[2]), "=r"(q[3]) : "r"(addr));
}
__device__ __forceinline__ void mma_bf16(float* c, const uint32_t* a,
                                         uint32_t b0, uint32_t b1) {
    asm volatile(
        "mma.sync.aligned.m16n8k16.row.col.f32.bf16.bf16.f32 "
        "{%0,%1,%2,%3}, {%4,%5,%6,%7}, {%8,%9}, {%0,%1,%2,%3};"
        : "+f"(c[0]), "+f"(c[1]), "+f"(c[2]), "+f"(c[3])
        : "r"(a[0]), "r"(a[1]), "r"(a[2]), "r"(a[3]), "r"(b0), "r"(b1));
}
__device__ __forceinline__ uint32_t pack2(__nv_bfloat16 a, __nv_bfloat16 b) {
    __nv_bfloat162 t;
    t.x = a; t.y = b;
    return *reinterpret_cast<uint32_t*>(&t);
}
__device__ __forceinline__ void split4(float4 v, uint2& hi, uint2& lo) {
    __nv_bfloat16 hx = __float2bfloat16_rn(v.x);
    __nv_bfloat16 hy = __float2bfloat16_rn(v.y);
    __nv_bfloat16 hz = __float2bfloat16_rn(v.z);
    __nv_bfloat16 hw = __float2bfloat16_rn(v.w);
    hi = make_uint2(pack2(hx, hy), pack2(hz, hw));
    lo = make_uint2(
        pack2(__float2bfloat16_rn(v.x - __bfloat162float(hx)),
              __float2bfloat16_rn(v.y - __bfloat162float(hy))),
        pack2(__float2bfloat16_rn(v.z - __bfloat162float(hz)),
              __float2bfloat16_rn(v.w - __bfloat162float(hw))));
}

// ---------------------------------------------------------------------------
// 1024x1024 transpose: WT[n][k] = W[k][n]
// ---------------------------------------------------------------------------
__global__ __launch_bounds__(256) void transpose_k(
    const float* __restrict__ in, float* __restrict__ out)
{
    __shared__ float t[32][33];
    int x = blockIdx.x * 32 + threadIdx.x;
    int y = blockIdx.y * 32 + threadIdx.y;
#pragma unroll
    for (int j = 0; j < 32; j += 8)
        t[threadIdx.y + j][threadIdx.x] = in[(size_t)(y + j) * 1024 + x];
    __syncthreads();
    int xo = blockIdx.y * 32 + threadIdx.x;
    int yo = blockIdx.x * 32 + threadIdx.y;
#pragma unroll
    for (int j = 0; j < 32; j += 8)
        out[(size_t)(yo + j) * 1024 + xo] = t[threadIdx.x][threadIdx.y + j];
}

// ---------------------------------------------------------------------------
// bf16x3 GEMM via mma.sync (unchanged from R4, validated).
// ---------------------------------------------------------------------------
static const int PANEL = 2080;               // 128*16 + 32 pad
static const int AHI = 0;
static const int ALO = 4 * PANEL;
static const int BHI = 8 * PANEL;
static const int BLO = 12 * PANEL;
static const int BUFSZ = 16 * PANEL;
static const int GEMM_SMEM = 2 * BUFSZ;

__global__ __launch_bounds__(256) void gemm_bf16x3_kernel(
    const float* __restrict__ A, const float* __restrict__ BT,
    const float* __restrict__ bias, float* __restrict__ C)
{
    extern __shared__ __align__(16) char smem[];
    const uint32_t sbase = smem_u32(smem);
    const int tid = threadIdx.x;
    const int wid = tid >> 5;
    const int lane = tid & 31;
    const int wm = (wid >> 1) * 32;
    const int wn = (wid & 1) * 64;
    const int brow = blockIdx.y * 128;
    const int bcol = blockIdx.x * 128;

    const float* Ap = A + (size_t)brow * 1024;
    const float* Bp = BT + (size_t)bcol * 1024;

    float c[2][8][4];
#pragma unroll
    for (int mt = 0; mt < 2; ++mt)
#pragma unroll
        for (int nt = 0; nt < 8; ++nt)
#pragma unroll
            for (int i = 0; i < 4; ++i) c[mt][nt][i] = 0.0f;

    float4 ra[4], rb[4];
    auto load_chunk = [&](int kbase) {
#pragma unroll
        for (int i = 0; i < 4; ++i) {
            int id = tid + i * 256;
            int row = id >> 3, f4 = id & 7;
            ra[i] = *(const float4*)(Ap + (size_t)row * 1024 + kbase + f4 * 4);
            rb[i] = *(const float4*)(Bp + (size_t)row * 1024 + kbase + f4 * 4);
        }
    };
    auto store_chunk = [&](int buf) {
        char* bp = smem + buf * BUFSZ;
#pragma unroll
        for (int i = 0; i < 4; ++i) {
            int id = tid + i * 256;
            int row = id >> 3, f4 = id & 7;
            int g = f4 >> 1, half = f4 & 1;
            int off = g * PANEL + row * 16 + half * 8;
            uint2 hi, lo;
            split4(ra[i], hi, lo);
            *(uint2*)(bp + AHI + off) = hi;
            *(uint2*)(bp + ALO + off) = lo;
            split4(rb[i], hi, lo);
            *(uint2*)(bp + BHI + off) = hi;
            *(uint2*)(bp + BLO + off) = lo;
        }
    };

    load_chunk(0);
    store_chunk(0);
    __syncthreads();

    for (int ch = 0; ch < 32; ++ch) {
        const int buf = ch & 1;
        if (ch + 1 < 32) load_chunk((ch + 1) * 32);

        const uint32_t bb = sbase + buf * BUFSZ;
#pragma unroll
        for (int ks = 0; ks < 2; ++ks) {
            const int g0 = ks * 2;
            uint32_t Af[2][2][4];
            uint32_t Bf[2][2][2][4];
#pragma unroll
            for (int s = 0; s < 2; ++s) {
                const uint32_t aoff = bb + (s ? ALO : AHI);
                const uint32_t boff = bb + (s ? BLO : BHI);
#pragma unroll
                for (int gg = 0; gg < 2; ++gg) {
                    ldm4(Af[s][gg],
                         aoff + (g0 + gg) * PANEL + (wm + lane) * 16);
#pragma unroll
                    for (int ng = 0; ng < 2; ++ng)
                        ldm4(Bf[s][gg][ng],
                             boff + (g0 + gg) * PANEL + (wn + ng * 32 + lane) * 16);
                }
            }
#pragma unroll
            for (int mt = 0; mt < 2; ++mt) {
                uint32_t ah[4] = {Af[0][0][mt * 2], Af[0][0][mt * 2 + 1],
                                  Af[0][1][mt * 2], Af[0][1][mt * 2 + 1]};
                uint32_t al[4] = {Af[1][0][mt * 2], Af[1][0][mt * 2 + 1],
                                  Af[1][1][mt * 2], Af[1][1][mt * 2 + 1]};
#pragma unroll
                for (int nt = 0; nt < 8; ++nt) {
                    const int ng = nt >> 2, q = nt & 3;
                    uint32_t bh0 = Bf[0][0][ng][q], bh1 = Bf[0][1][ng][q];
                    uint32_t bl0 = Bf[1][0][ng][q], bl1 = Bf[1][1][ng][q];
                    mma_bf16(c[mt][nt], ah, bh0, bh1);
                    mma_bf16(c[mt][nt], ah, bl0, bl1);
                    mma_bf16(c[mt][nt], al, bh0, bh1);
                }
            }
        }
        __syncthreads();
        if (ch + 1 < 32) {
            store_chunk(buf ^ 1);
            __syncthreads();
        }
    }

    const int r0b = brow + wm + (lane >> 2);
    const int colb = bcol + wn + 2 * (lane & 3);
#pragma unroll
    for (int mt = 0; mt < 2; ++mt) {
#pragma unroll
        for (int nt = 0; nt < 8; ++nt) {
            const int col = colb + nt * 8;
            const float2 bi = *(const float2*)(bias + col);
            const int r0 = r0b + mt * 16;
            float2 v0 = make_float2(c[mt][nt][0] + bi.x, c[mt][nt][1] + bi.y);
            float2 v1 = make_float2(c[mt][nt][2] + bi.x, c[mt][nt][3] + bi.y);
            *(float2*)(C + (size_t)r0 * 1024 + col) = v0;
            *(float2*)(C + (size_t)(r0 + 8) * 1024 + col) = v1;
        }
    }
}

// ---------------------------------------------------------------------------
// Tensor-core flash attention (bf16x3 via mma.sync).
// Block: 128 q-rows of one (b,h); 8 warps x 16 rows; all 64 keys per warp
// (softmax reductions warp-local). K-tiles of 64 keys.
// Mask FIX (R6): apply s += (1 - vn*vm)*(-1e6). Valid pairs add EXACTLY 0.0;
// the R5 form (s - 1e6 + vn*vm*1e6) quantized logits at ulp(1e6)=0.0625.
// ---------------------------------------------------------------------------
static const int QPNL = 2080;                 // 128 rows * 16B + pad
static const int KPNL = 1056;                 // 64 rows * 16B + pad
static const int VSTR = 144;                  // 64 keys x (128B row + 16 pad)
static const int SQHI = 0;
static const int SQLO = 8 * QPNL;             // 16640
static const int SKHI = 16 * QPNL;            // 33280
static const int SKLO = SKHI + 8 * KPNL;      // 41728
static const int SVHI = SKLO + 8 * KPNL;      // 50176
static const int SVLO = SVHI + 64 * VSTR;     // 59392
static const int SAM  = SVLO + 64 * VSTR;     // 68608 (key valid flags 1.0/0.0)
static const int ATTN_SMEM = SAM + 64 * 4;    // 68864

__global__ __launch_bounds__(256) void attn_mma_kernel(
    const float* __restrict__ Q, const float* __restrict__ K,
    const float* __restrict__ V, const int* __restrict__ pad,
    float* __restrict__ O)
{
    extern __shared__ __align__(16) char smem[];
    const uint32_t sb = smem_u32(smem);
    const int tid = threadIdx.x;
    const int wid = tid >> 5;
    const int lane = tid & 31;
    const int wm = wid * 16;          // warp's first q-row within tile
    const int bh = blockIdx.y;
    const int b = bh >> 4;
    const int h = bh & 15;
    const int qbase = blockIdx.x * 128;

    // ---- stage Q tile (scaled by 1/8) into hi/lo panels ----
#pragma unroll
    for (int i = 0; i < 8; ++i) {
        int id = tid + i * 256;       // 0..2047 = 128 rows x 16 f4
        int row = id >> 4, f4 = id & 15;
        float4 v = *(const float4*)(Q + ((size_t)(b * Nn + qbase + row)) * Dd +
                                    h * 64 + f4 * 4);
        v.x *= 0.125f; v.y *= 0.125f; v.z *= 0.125f; v.w *= 0.125f;
        uint2 hi, lo;
        split4(v, hi, lo);
        int off = (f4 >> 1) * QPNL + row * 16 + (f4 & 1) * 8;
        *(uint2*)(smem + SQHI + off) = hi;
        *(uint2*)(smem + SQLO + off) = lo;
    }
    __syncthreads();

    // ---- Q fragments to registers (per d-chunk of 16) ----
    uint32_t qh[4][4], ql[4][4];
#pragma unroll
    for (int kc = 0; kc < 4; ++kc) {
        uint32_t addr = sb + SQHI + (2 * kc + (lane >> 4)) * QPNL +
                        (wm + (lane & 15)) * 16;
        ldm4(qh[kc], addr);
        ldm4(ql[kc], addr + (SQLO - SQHI));
    }

    const int r = lane >> 2;
    const int qn0 = qbase + wm + r;
    const int qn1 = qn0 + 8;
    const float vn0 = (pad[b * Nn + qn0] == 0) ? 1.0f : 0.0f;
    const float vn1 = (pad[b * Nn + qn1] == 0) ? 1.0f : 0.0f;

    float o[8][4];
#pragma unroll
    for (int nd = 0; nd < 8; ++nd)
#pragma unroll
        for (int i = 0; i < 4; ++i) o[nd][i] = 0.0f;
    float m0 = -1e30f, m1 = -1e30f, l0 = 0.0f, l1 = 0.0f;

    for (int kt = 0; kt < Nn; kt += 64) {
        __syncthreads();   // previous tile fully consumed
        // ---- stage K (panels) and V (row-major, 144B stride), hi/lo ----
#pragma unroll
        for (int i = 0; i < 4; ++i) {
            int id = tid + i * 256;   // 0..1023 = 64 rows x 16 f4
            int row = id >> 4, f4 = id & 15;
            size_t g = ((size_t)(b * Nn + kt + row)) * Dd + h * 64 + f4 * 4;
            uint2 hi, lo;
            split4(*(const float4*)(K + g), hi, lo);
            int koff = (f4 >> 1) * KPNL + row * 16 + (f4 & 1) * 8;
            *(uint2*)(smem + SKHI + koff) = hi;
            *(uint2*)(smem + SKLO + koff) = lo;
            split4(*(const float4*)(V + g), hi, lo);
            int voff = row * VSTR + f4 * 8;
            *(uint2*)(smem + SVHI + voff) = hi;
            *(uint2*)(smem + SVLO + voff) = lo;
        }
        if (tid < 64)
            *(float*)(smem + SAM + tid * 4) =
                (pad[b * Nn + kt + tid] == 0) ? 1.0f : 0.0f;
        __syncthreads();

        // ---- S = Q K^T (bf16x3) ----
        float s[8][4];
#pragma unroll
        for (int nt = 0; nt < 8; ++nt)
#pragma unroll
            for (int i = 0; i < 4; ++i) s[nt][i] = 0.0f;

#pragma unroll
        for (int kc = 0; kc < 4; ++kc) {
            uint32_t b0h[4], b4h[4], b1h[4], b5h[4];
            uint32_t b0l[4], b4l[4], b1l[4], b5l[4];
            uint32_t p0 = sb + SKHI + (2 * kc) * KPNL + lane * 16;
            uint32_t p1 = sb + SKHI + (2 * kc + 1) * KPNL + lane * 16;
            ldm4(b0h, p0);
            ldm4(b4h, p0 + 32 * 16);
            ldm4(b1h, p1);
            ldm4(b5h, p1 + 32 * 16);
            ldm4(b0l, p0 + (SKLO - SKHI));
            ldm4(b4l, p0 + 32 * 16 + (SKLO - SKHI));
            ldm4(b1l, p1 + (SKLO - SKHI));
            ldm4(b5l, p1 + 32 * 16 + (SKLO - SKHI));
#pragma unroll
            for (int nt = 0; nt < 8; ++nt) {
                uint32_t kh0 = (nt < 4) ? b0h[nt] : b4h[nt - 4];
                uint32_t kh1 = (nt < 4) ? b1h[nt] : b5h[nt - 4];
                uint32_t kl0 = (nt < 4) ? b0l[nt] : b4l[nt - 4];
                uint32_t kl1 = (nt < 4) ? b1l[nt] : b5l[nt - 4];
                mma_bf16(s[nt], qh[kc], kh0, kh1);
                mma_bf16(s[nt], qh[kc], kl0, kl1);
                mma_bf16(s[nt], ql[kc], kh0, kh1);
            }
        }

        // ---- mask (exact-zero form) + online softmax (warp-local) ----
        float tm0 = -1e30f, tm1 = -1e30f;
#pragma unroll
        for (int nt = 0; nt < 8; ++nt) {
            float2 vm = *(const float2*)(smem + SAM +
                                         (nt * 8 + 2 * (lane & 3)) * 4);
            s[nt][0] = fmaf(1.0f - vn0 * vm.x, -1e6f, s[nt][0]);
            s[nt][1] = fmaf(1.0f - vn0 * vm.y, -1e6f, s[nt][1]);
            s[nt][2] = fmaf(1.0f - vn1 * vm.x, -1e6f, s[nt][2]);
            s[nt][3] = fmaf(1.0f - vn1 * vm.y, -1e6f, s[nt][3]);
            tm0 = fmaxf(tm0, fmaxf(s[nt][0], s[nt][1]));
            tm1 = fmaxf(tm1, fmaxf(s[nt][2], s[nt][3]));
        }
        tm0 = fmaxf(tm0, __shfl_xor_sync(0xffffffffu, tm0, 1));
        tm0 = fmaxf(tm0, __shfl_xor_sync(0xffffffffu, tm0, 2));
        tm1 = fmaxf(tm1, __shfl_xor_sync(0xffffffffu, tm1, 1));
        tm1 = fmaxf(tm1, __shfl_xor_sync(0xffffffffu, tm1, 2));

        float m0n = fmaxf(m0, tm0), m1n = fmaxf(m1, tm1);
        float a0 = __expf(m0 - m0n), a1 = __expf(m1 - m1n);
        m0 = m0n; m1 = m1n;

        float sum0 = 0.0f, sum1 = 0.0f;
#pragma unroll
        for (int nt = 0; nt < 8; ++nt) {
            s[nt][0] = __expf(s[nt][0] - m0);
            s[nt][1] = __expf(s[nt][1] - m0);
            s[nt][2] = __expf(s[nt][2] - m1);
            s[nt][3] = __expf(s[nt][3] - m1);
            sum0 += s[nt][0] + s[nt][1];
            sum1 += s[nt][2] + s[nt][3];
        }
        sum0 += __shfl_xor_sync(0xffffffffu, sum0, 1);
        sum0 += __shfl_xor_sync(0xffffffffu, sum0, 2);
        sum1 += __shfl_xor_sync(0xffffffffu, sum1, 1);
        sum1 += __shfl_xor_sync(0xffffffffu, sum1, 2);
        l0 = l0 * a0 + sum0;
        l1 = l1 * a1 + sum1;
#pragma unroll
        for (int nd = 0; nd < 8; ++nd) {
            o[nd][0] *= a0; o[nd][1] *= a0;
            o[nd][2] *= a1; o[nd][3] *= a1;
        }

        // ---- O += P V (bf16x3), P from S frags ----
#pragma unroll
        for (int kc = 0; kc < 4; ++kc) {
            uint32_t ph[4], pl[4];
            {
                const float* pa = s[2 * kc];
                const float* pb = s[2 * kc + 1];
                __nv_bfloat16 h0 = __float2bfloat16_rn(pa[0]);
                __nv_bfloat16 h1 = __float2bfloat16_rn(pa[1]);
                __nv_bfloat16 h2 = __float2bfloat16_rn(pa[2]);
                __nv_bfloat16 h3 = __float2bfloat16_rn(pa[3]);
                __nv_bfloat16 h4 = __float2bfloat16_rn(pb[0]);
                __nv_bfloat16 h5 = __float2bfloat16_rn(pb[1]);
                __nv_bfloat16 h6 = __float2bfloat16_rn(pb[2]);
                __nv_bfloat16 h7 = __float2bfloat16_rn(pb[3]);
                ph[0] = pack2(h0, h1);
                ph[1] = pack2(h2, h3);
                ph[2] = pack2(h4, h5);
                ph[3] = pack2(h6, h7);
                pl[0] = pack2(__float2bfloat16_rn(pa[0] - __bfloat162float(h0)),
                              __float2bfloat16_rn(pa[1] - __bfloat162float(h1)));
                pl[1] = pack2(__float2bfloat16_rn(pa[2] - __bfloat162float(h2)),
                              __float2bfloat16_rn(pa[3] - __bfloat162float(h3)));
                pl[2] = pack2(__float2bfloat16_rn(pb[0] - __bfloat162float(h4)),
                              __float2bfloat16_rn(pb[1] - __bfloat162float(h5)));
                pl[3] = pack2(__float2bfloat16_rn(pb[2] - __bfloat162float(h6)),
                              __float2bfloat16_rn(pb[3] - __bfloat162float(h7)));
            }
#pragma unroll
            for (int jj = 0; jj < 4; ++jj) {
                uint32_t vh[4], vl[4];
                uint32_t va = sb + SVHI + (kc * 16 + (lane & 15)) * VSTR +
                              (2 * jj + (lane >> 4)) * 16;
                ldm4t(vh, va);
                ldm4t(vl, va + (SVLO - SVHI));
                mma_bf16(o[2 * jj], ph, vh[0], vh[1]);
                mma_bf16(o[2 * jj], ph, vl[0], vl[1]);
                mma_bf16(o[2 * jj], pl, vh[0], vh[1]);
                mma_bf16(o[2 * jj + 1], ph, vh[2], vh[3]);
                mma_bf16(o[2 * jj + 1], ph, vl[2], vl[3]);
                mma_bf16(o[2 * jj + 1], pl, vh[2], vh[3]);
            }
        }
    }

    // ---- epilogue: O /= l, store fp32 ----
    const float inv0 = 1.0f / l0, inv1 = 1.0f / l1;
    const size_t row0 = (size_t)(b * Nn + qn0) * Dd;
    const size_t row1 = (size_t)(b * Nn + qn1) * Dd;
#pragma unroll
    for (int nd = 0; nd < 8; ++nd) {
        const int col = h * 64 + nd * 8 + 2 * (lane & 3);
        *(float2*)(O + row0 + col) =
            make_float2(o[nd][0] * inv0, o[nd][1] * inv0);
        *(float2*)(O + row1 + col) =
            make_float2(o[nd][2] * inv1, o[nd][3] * inv1);
    }
}

// ---------------------------------------------------------------------------
// Launch
// ---------------------------------------------------------------------------
extern "C" void kernel_launch(void* const* d_in, const int* in_sizes, int n_in,
                              void* d_out, int out_size)
{
    const float* x  = (const float*)d_in[0];
    const int*   pd = (const int*)d_in[1];
    const float* wq = (const float*)d_in[2];
    const float* bq = (const float*)d_in[3];
    const float* wk = (const float*)d_in[4];
    const float* bk = (const float*)d_in[5];
    const float* wv = (const float*)d_in[6];
    const float* bv = (const float*)d_in[7];
    const float* wo = (const float*)d_in[8];
    const float* bo = (const float*)d_in[9];
    float* out = (float*)d_out;

    float *Q, *K, *V, *O, *WT;
    cudaGetSymbolAddress((void**)&Q, g_Q);
    cudaGetSymbolAddress((void**)&K, g_K);
    cudaGetSymbolAddress((void**)&V, g_V);
    cudaGetSymbolAddress((void**)&O, g_O);
    cudaGetSymbolAddress((void**)&WT, g_WT);

    cudaFuncSetAttribute(gemm_bf16x3_kernel,
                         cudaFuncAttributeMaxDynamicSharedMemorySize, GEMM_SMEM);
    cudaFuncSetAttribute(attn_mma_kernel,
                         cudaFuncAttributeMaxDynamicSharedMemorySize, ATTN_SMEM);

    dim3 tgrid(32, 32), tblk(32, 8);
    transpose_k<<<tgrid, tblk>>>(wq, WT + 0 * 1024 * 1024);
    transpose_k<<<tgrid, tblk>>>(wk, WT + 1 * 1024 * 1024);
    transpose_k<<<tgrid, tblk>>>(wv, WT + 2 * 1024 * 1024);
    transpose_k<<<tgrid, tblk>>>(wo, WT + 3 * 1024 * 1024);

    dim3 ggrid(Dd / 128, Mm / 128); // (8, 64)
    gemm_bf16x3_kernel<<<ggrid, 256, GEMM_SMEM>>>(x, WT + 0 * 1024 * 1024, bq, Q);
    gemm_bf16x3_kernel<<<ggrid, 256, GEMM_SMEM>>>(x, WT + 1 * 1024 * 1024, bk, K);
    gemm_bf16x3_kernel<<<ggrid, 256, GEMM_SMEM>>>(x, WT + 2 * 1024 * 1024, bv, V);

    dim3 agrid(Nn / 128, Bb * 16); // (16, 64)
    attn_mma_kernel<<<agrid, 256, ATTN_SMEM>>>(Q, K, V, pd, O);

    gemm_bf16x3_kernel<<<ggrid, 256, GEMM_SMEM>>>(O, WT + 3 * 1024 * 1024, bo, out);
}

// round 10
// speedup vs baseline: 2.7376x; 1.1014x over previous
#include <cuda_runtime.h>
#include <cuda_fp16.h>
#include <cstdint>
#include <math.h>

// Shapes fixed by dataset: x:(4,2048,1024) f32, pad:(4,2048) i32,
// w*:(1024,1024) f32, b*:(1024) f32, h=16 (depth 64). out:(4,2048,1024) f32.
static const int Bb = 4;
static const int Nn = 2048;
static const int Dd = 1024;
static const int Mm = Bb * Nn; // 8192

// Scratch (no allocs allowed).
__device__ float g_Q[8192 * 1024];
__device__ float g_K[8192 * 1024];
__device__ float g_V[8192 * 1024];
__device__ float g_O[8192 * 1024];
__device__ float g_WT[4 * 1024 * 1024];

// ---------------------------------------------------------------------------
// Helpers (sm_80-era PTX: mma.sync + ldmatrix)
// ---------------------------------------------------------------------------
__device__ __forceinline__ uint32_t smem_u32(const void* p) {
    uint32_t a;
    asm("{ .reg .u64 t; cvta.to.shared.u64 t, %1; cvt.u32.u64 %0, t; }"
        : "=r"(a) : "l"(p));
    return a;
}
__device__ __forceinline__ void ldm4(uint32_t* q, uint32_t addr) {
    asm volatile("ldmatrix.sync.aligned.m8n8.x4.shared.b16 {%0,%1,%2,%3}, [%4];"
                 : "=r"(q[0]), "=r"(q[1]), "=r"(q[2]), "=r"(q[3]) : "r"(addr));
}
__device__ __forceinline__ void ldm4t(uint32_t* q, uint32_t addr) {
    asm volatile("ldmatrix.sync.aligned.m8n8.x4.trans.shared.b16 {%0,%1,%2,%3}, [%4];"
                 : "=r"(q[0]), "=r"(q[1]), "=r"(q[2]), "=r"(q[3]) : "r"(addr));
}
// fp16 mma, fp32 accumulate. NOT volatile: ptxas may reorder independent mmas
// to hide HMMA latency.
__device__ __forceinline__ void mma_f16(float* c, const uint32_t* a,
                                        uint32_t b0, uint32_t b1) {
    asm("mma.sync.aligned.m16n8k16.row.col.f32.f16.f16.f32 "
        "{%0,%1,%2,%3}, {%4,%5,%6,%7}, {%8,%9}, {%0,%1,%2,%3};"
        : "+f"(c[0]), "+f"(c[1]), "+f"(c[2]), "+f"(c[3])
        : "r"(a[0]), "r"(a[1]), "r"(a[2]), "r"(a[3]), "r"(b0), "r"(b1));
}
__device__ __forceinline__ uint32_t pack2h(__half a, __half b) {
    __half2 t;
    t.x = a; t.y = b;
    return *reinterpret_cast<uint32_t*>(&t);
}
// Exact split: v = hi + lo (both fp16), elementwise.
__device__ __forceinline__ void split4h(float4 v, uint2& hi, uint2& lo) {
    __half hx = __float2half_rn(v.x);
    __half hy = __float2half_rn(v.y);
    __half hz = __float2half_rn(v.z);
    __half hw = __float2half_rn(v.w);
    hi = make_uint2(pack2h(hx, hy), pack2h(hz, hw));
    lo = make_uint2(
        pack2h(__float2half_rn(v.x - __half2float(hx)),
               __float2half_rn(v.y - __half2float(hy))),
        pack2h(__float2half_rn(v.z - __half2float(hz)),
               __float2half_rn(v.w - __half2float(hw))));
}

// ---------------------------------------------------------------------------
// 1024x1024 transpose: WT[n][k] = W[k][n]
// ---------------------------------------------------------------------------
__global__ __launch_bounds__(256) void transpose_k(
    const float* __restrict__ in, float* __restrict__ out)
{
    __shared__ float t[32][33];
    int x = blockIdx.x * 32 + threadIdx.x;
    int y = blockIdx.y * 32 + threadIdx.y;
#pragma unroll
    for (int j = 0; j < 32; j += 8)
        t[threadIdx.y + j][threadIdx.x] = in[(size_t)(y + j) * 1024 + x];
    __syncthreads();
    int xo = blockIdx.y * 32 + threadIdx.x;
    int yo = blockIdx.x * 32 + threadIdx.y;
#pragma unroll
    for (int j = 0; j < 32; j += 8)
        out[(size_t)(yo + j) * 1024 + xo] = t[threadIdx.x][threadIdx.y + j];
}

// ---------------------------------------------------------------------------
// fp16 3-term GEMM (near-exact: drops only Al@Bl, ~(5e-4)^2 relative):
//   C = Ah@Bh + Ah@Bl + Al@Bh + bias,  BT[n][k] = W[k][n].
// Term-major ordering: 16 independent mmas per sweep.
// ---------------------------------------------------------------------------
static const int PANEL = 2080;               // 128*16 + 32 pad
static const int GAHI = 0;
static const int GALO = 4 * PANEL;
static const int GBHI = 8 * PANEL;
static const int GBLO = 12 * PANEL;
static const int BUFSZ = 16 * PANEL;         // 33280
static const int GEMM_SMEM = 2 * BUFSZ;      // 66560

__global__ __launch_bounds__(256) void gemm_f16x3_kernel(
    const float* __restrict__ A, const float* __restrict__ BT,
    const float* __restrict__ bias, float* __restrict__ C)
{
    extern __shared__ __align__(16) char smem[];
    const uint32_t sbase = smem_u32(smem);
    const int tid = threadIdx.x;
    const int wid = tid >> 5;
    const int lane = tid & 31;
    const int wm = (wid >> 1) * 32;
    const int wn = (wid & 1) * 64;
    const int brow = blockIdx.y * 128;
    const int bcol = blockIdx.x * 128;

    const float* Ap = A + (size_t)brow * 1024;
    const float* Bp = BT + (size_t)bcol * 1024;

    float c[2][8][4];
#pragma unroll
    for (int mt = 0; mt < 2; ++mt)
#pragma unroll
        for (int nt = 0; nt < 8; ++nt)
#pragma unroll
            for (int i = 0; i < 4; ++i) c[mt][nt][i] = 0.0f;

    float4 ra[4], rb[4];
    auto load_chunk = [&](int kbase) {
#pragma unroll
        for (int i = 0; i < 4; ++i) {
            int id = tid + i * 256;
            int row = id >> 3, f4 = id & 7;
            ra[i] = *(const float4*)(Ap + (size_t)row * 1024 + kbase + f4 * 4);
            rb[i] = *(const float4*)(Bp + (size_t)row * 1024 + kbase + f4 * 4);
        }
    };
    auto store_chunk = [&](int buf) {
        char* bp = smem + buf * BUFSZ;
#pragma unroll
        for (int i = 0; i < 4; ++i) {
            int id = tid + i * 256;
            int row = id >> 3, f4 = id & 7;
            int off = (f4 >> 1) * PANEL + row * 16 + (f4 & 1) * 8;
            uint2 hi, lo;
            split4h(ra[i], hi, lo);
            *(uint2*)(bp + GAHI + off) = hi;
            *(uint2*)(bp + GALO + off) = lo;
            split4h(rb[i], hi, lo);
            *(uint2*)(bp + GBHI + off) = hi;
            *(uint2*)(bp + GBLO + off) = lo;
        }
    };

    load_chunk(0);
    store_chunk(0);
    __syncthreads();

    for (int ch = 0; ch < 32; ++ch) {
        const int buf = ch & 1;
        if (ch + 1 < 32) load_chunk((ch + 1) * 32);

        const uint32_t bb = sbase + buf * BUFSZ;
#pragma unroll
        for (int ks = 0; ks < 2; ++ks) {
            const int g0 = ks * 2;
            uint32_t Afh[2][4], Afl[2][4];       // [gg][quad]
            uint32_t Bfh[2][2][4], Bfl[2][2][4]; // [gg][ng][quad]
#pragma unroll
            for (int gg = 0; gg < 2; ++gg) {
                uint32_t arow = bb + (g0 + gg) * PANEL + (wm + lane) * 16;
                ldm4(Afh[gg], arow + GAHI);
                ldm4(Afl[gg], arow + GALO);
#pragma unroll
                for (int ng = 0; ng < 2; ++ng) {
                    uint32_t brow_ = bb + (g0 + gg) * PANEL +
                                     (wn + ng * 32 + lane) * 16;
                    ldm4(Bfh[gg][ng], brow_ + GBHI);
                    ldm4(Bfl[gg][ng], brow_ + GBLO);
                }
            }
            uint32_t ah[2][4], al[2][4];
#pragma unroll
            for (int mt = 0; mt < 2; ++mt) {
                ah[mt][0] = Afh[0][mt * 2]; ah[mt][1] = Afh[0][mt * 2 + 1];
                ah[mt][2] = Afh[1][mt * 2]; ah[mt][3] = Afh[1][mt * 2 + 1];
                al[mt][0] = Afl[0][mt * 2]; al[mt][1] = Afl[0][mt * 2 + 1];
                al[mt][2] = Afl[1][mt * 2]; al[mt][3] = Afl[1][mt * 2 + 1];
            }
            // term-major: 3 sweeps of 16 independent mmas
#pragma unroll
            for (int mt = 0; mt < 2; ++mt)
#pragma unroll
                for (int nt = 0; nt < 8; ++nt)
                    mma_f16(c[mt][nt], ah[mt],
                            Bfh[0][nt >> 2][nt & 3], Bfh[1][nt >> 2][nt & 3]);
#pragma unroll
            for (int mt = 0; mt < 2; ++mt)
#pragma unroll
                for (int nt = 0; nt < 8; ++nt)
                    mma_f16(c[mt][nt], ah[mt],
                            Bfl[0][nt >> 2][nt & 3], Bfl[1][nt >> 2][nt & 3]);
#pragma unroll
            for (int mt = 0; mt < 2; ++mt)
#pragma unroll
                for (int nt = 0; nt < 8; ++nt)
                    mma_f16(c[mt][nt], al[mt],
                            Bfh[0][nt >> 2][nt & 3], Bfh[1][nt >> 2][nt & 3]);
        }
        __syncthreads();
        if (ch + 1 < 32) {
            store_chunk(buf ^ 1);
            __syncthreads();
        }
    }

    const int r0b = brow + wm + (lane >> 2);
    const int colb = bcol + wn + 2 * (lane & 3);
#pragma unroll
    for (int mt = 0; mt < 2; ++mt) {
#pragma unroll
        for (int nt = 0; nt < 8; ++nt) {
            const int col = colb + nt * 8;
            const float2 bi = *(const float2*)(bias + col);
            const int r0 = r0b + mt * 16;
            float2 v0 = make_float2(c[mt][nt][0] + bi.x, c[mt][nt][1] + bi.y);
            float2 v1 = make_float2(c[mt][nt][2] + bi.x, c[mt][nt][3] + bi.y);
            *(float2*)(C + (size_t)r0 * 1024 + col) = v0;
            *(float2*)(C + (size_t)(r0 + 8) * 1024 + col) = v1;
        }
    }
}

// ---------------------------------------------------------------------------
// Tensor-core flash attention, fp16 3-term EVERYWHERE (R9 lesson: the QK^T
// K-rounding error is NOT softmax-attenuated; 2-term there alone = 1.1e-3).
//   S = qh@Kh + qh@Kl + ql@Kh
//   O += Ph@Vh + Ph@Vl + Pl@Vh
// Mask: s += (1 - vn*vm)*(-1e6)  (exact-zero form, R6-validated).
// ---------------------------------------------------------------------------
static const int QPNL = 2080;                 // 128 rows * 16B + pad
static const int KPNL = 1056;                 // 64 rows * 16B + pad
static const int VSTR = 144;                  // 128B row + 16 pad
static const int SQHI = 0;
static const int SQLO = 8 * QPNL;             // 16640
static const int SKHI = 16 * QPNL;            // 33280
static const int SKLO = SKHI + 8 * KPNL;      // 41728
static const int SVHI = SKLO + 8 * KPNL;      // 50176
static const int SVLO = SVHI + 64 * VSTR;     // 59392
static const int SAM  = SVLO + 64 * VSTR;     // 68608 (key valid flags)
static const int ATTN_SMEM = SAM + 64 * 4;    // 68864

__global__ __launch_bounds__(256) void attn_mma_kernel(
    const float* __restrict__ Q, const float* __restrict__ K,
    const float* __restrict__ V, const int* __restrict__ pad,
    float* __restrict__ O)
{
    extern __shared__ __align__(16) char smem[];
    const uint32_t sb = smem_u32(smem);
    const int tid = threadIdx.x;
    const int wid = tid >> 5;
    const int lane = tid & 31;
    const int wm = wid * 16;
    const int bh = blockIdx.y;
    const int b = bh >> 4;
    const int h = bh & 15;
    const int qbase = blockIdx.x * 128;

    // ---- stage Q tile (x 1/8) into hi/lo fp16 panels ----
#pragma unroll
    for (int i = 0; i < 8; ++i) {
        int id = tid + i * 256;
        int row = id >> 4, f4 = id & 15;
        float4 v = *(const float4*)(Q + ((size_t)(b * Nn + qbase + row)) * Dd +
                                    h * 64 + f4 * 4);
        v.x *= 0.125f; v.y *= 0.125f; v.z *= 0.125f; v.w *= 0.125f;
        uint2 hi, lo;
        split4h(v, hi, lo);
        int off = (f4 >> 1) * QPNL + row * 16 + (f4 & 1) * 8;
        *(uint2*)(smem + SQHI + off) = hi;
        *(uint2*)(smem + SQLO + off) = lo;
    }
    __syncthreads();

    uint32_t qh[4][4], ql[4][4];
#pragma unroll
    for (int kc = 0; kc < 4; ++kc) {
        uint32_t addr = sb + SQHI + (2 * kc + (lane >> 4)) * QPNL +
                        (wm + (lane & 15)) * 16;
        ldm4(qh[kc], addr);
        ldm4(ql[kc], addr + (SQLO - SQHI));
    }

    const int r = lane >> 2;
    const int qn0 = qbase + wm + r;
    const int qn1 = qn0 + 8;
    const float vn0 = (pad[b * Nn + qn0] == 0) ? 1.0f : 0.0f;
    const float vn1 = (pad[b * Nn + qn1] == 0) ? 1.0f : 0.0f;

    float o[8][4];
#pragma unroll
    for (int nd = 0; nd < 8; ++nd)
#pragma unroll
        for (int i = 0; i < 4; ++i) o[nd][i] = 0.0f;
    float m0 = -1e30f, m1 = -1e30f, l0 = 0.0f, l1 = 0.0f;

    for (int kt = 0; kt < Nn; kt += 64) {
        __syncthreads();
        // ---- stage K (hi+lo panels) and V (hi+lo rows) ----
#pragma unroll
        for (int i = 0; i < 4; ++i) {
            int id = tid + i * 256;
            int row = id >> 4, f4 = id & 15;
            size_t g = ((size_t)(b * Nn + kt + row)) * Dd + h * 64 + f4 * 4;
            uint2 hi, lo;
            split4h(*(const float4*)(K + g), hi, lo);
            int koff = (f4 >> 1) * KPNL + row * 16 + (f4 & 1) * 8;
            *(uint2*)(smem + SKHI + koff) = hi;
            *(uint2*)(smem + SKLO + koff) = lo;
            split4h(*(const float4*)(V + g), hi, lo);
            int voff = row * VSTR + f4 * 8;
            *(uint2*)(smem + SVHI + voff) = hi;
            *(uint2*)(smem + SVLO + voff) = lo;
        }
        if (tid < 64)
            *(float*)(smem + SAM + tid * 4) =
                (pad[b * Nn + kt + tid] == 0) ? 1.0f : 0.0f;
        __syncthreads();

        // ---- S = qh Kh + qh Kl + ql Kh ----
        float s[8][4];
#pragma unroll
        for (int nt = 0; nt < 8; ++nt)
#pragma unroll
            for (int i = 0; i < 4; ++i) s[nt][i] = 0.0f;

#pragma unroll
        for (int kc = 0; kc < 4; ++kc) {
            uint32_t b0h[4], b4h[4], b1h[4], b5h[4];
            uint32_t b0l[4], b4l[4], b1l[4], b5l[4];
            uint32_t p0 = sb + SKHI + (2 * kc) * KPNL + lane * 16;
            uint32_t p1 = sb + SKHI + (2 * kc + 1) * KPNL + lane * 16;
            ldm4(b0h, p0);
            ldm4(b4h, p0 + 32 * 16);
            ldm4(b1h, p1);
            ldm4(b5h, p1 + 32 * 16);
            ldm4(b0l, p0 + (SKLO - SKHI));
            ldm4(b4l, p0 + 32 * 16 + (SKLO - SKHI));
            ldm4(b1l, p1 + (SKLO - SKHI));
            ldm4(b5l, p1 + 32 * 16 + (SKLO - SKHI));
            // 3 term-major sweeps of 8 independent mmas
#pragma unroll
            for (int nt = 0; nt < 8; ++nt)
                mma_f16(s[nt], qh[kc],
                        (nt < 4) ? b0h[nt] : b4h[nt - 4],
                        (nt < 4) ? b1h[nt] : b5h[nt - 4]);
#pragma unroll
            for (int nt = 0; nt < 8; ++nt)
                mma_f16(s[nt], qh[kc],
                        (nt < 4) ? b0l[nt] : b4l[nt - 4],
                        (nt < 4) ? b1l[nt] : b5l[nt - 4]);
#pragma unroll
            for (int nt = 0; nt < 8; ++nt)
                mma_f16(s[nt], ql[kc],
                        (nt < 4) ? b0h[nt] : b4h[nt - 4],
                        (nt < 4) ? b1h[nt] : b5h[nt - 4]);
        }

        // ---- mask (exact-zero form) + online softmax ----
        float tm0 = -1e30f, tm1 = -1e30f;
#pragma unroll
        for (int nt = 0; nt < 8; ++nt) {
            float2 vm = *(const float2*)(smem + SAM +
                                         (nt * 8 + 2 * (lane & 3)) * 4);
            s[nt][0] = fmaf(1.0f - vn0 * vm.x, -1e6f, s[nt][0]);
            s[nt][1] = fmaf(1.0f - vn0 * vm.y, -1e6f, s[nt][1]);
            s[nt][2] = fmaf(1.0f - vn1 * vm.x, -1e6f, s[nt][2]);
            s[nt][3] = fmaf(1.0f - vn1 * vm.y, -1e6f, s[nt][3]);
            tm0 = fmaxf(tm0, fmaxf(s[nt][0], s[nt][1]));
            tm1 = fmaxf(tm1, fmaxf(s[nt][2], s[nt][3]));
        }
        tm0 = fmaxf(tm0, __shfl_xor_sync(0xffffffffu, tm0, 1));
        tm0 = fmaxf(tm0, __shfl_xor_sync(0xffffffffu, tm0, 2));
        tm1 = fmaxf(tm1, __shfl_xor_sync(0xffffffffu, tm1, 1));
        tm1 = fmaxf(tm1, __shfl_xor_sync(0xffffffffu, tm1, 2));

        float m0n = fmaxf(m0, tm0), m1n = fmaxf(m1, tm1);
        float a0 = __expf(m0 - m0n), a1 = __expf(m1 - m1n);
        m0 = m0n; m1 = m1n;

        float sum0 = 0.0f, sum1 = 0.0f;
#pragma unroll
        for (int nt = 0; nt < 8; ++nt) {
            s[nt][0] = __expf(s[nt][0] - m0);
            s[nt][1] = __expf(s[nt][1] - m0);
            s[nt][2] = __expf(s[nt][2] - m1);
            s[nt][3] = __expf(s[nt][3] - m1);
            sum0 += s[nt][0] + s[nt][1];
            sum1 += s[nt][2] + s[nt][3];
        }
        sum0 += __shfl_xor_sync(0xffffffffu, sum0, 1);
        sum0 += __shfl_xor_sync(0xffffffffu, sum0, 2);
        sum1 += __shfl_xor_sync(0xffffffffu, sum1, 1);
        sum1 += __shfl_xor_sync(0xffffffffu, sum1, 2);
        l0 = l0 * a0 + sum0;
        l1 = l1 * a1 + sum1;
#pragma unroll
        for (int nd = 0; nd < 8; ++nd) {
            o[nd][0] *= a0; o[nd][1] *= a0;
            o[nd][2] *= a1; o[nd][3] *= a1;
        }

        // ---- O += Ph Vh + Ph Vl + Pl Vh ----
#pragma unroll
        for (int kc = 0; kc < 4; ++kc) {
            uint32_t ph[4], pl[4];
            {
                const float* pa = s[2 * kc];
                const float* pb = s[2 * kc + 1];
                __half h0 = __float2half_rn(pa[0]);
                __half h1 = __float2half_rn(pa[1]);
                __half h2 = __float2half_rn(pa[2]);
                __half h3 = __float2half_rn(pa[3]);
                __half h4 = __float2half_rn(pb[0]);
                __half h5 = __float2half_rn(pb[1]);
                __half h6 = __float2half_rn(pb[2]);
                __half h7 = __float2half_rn(pb[3]);
                ph[0] = pack2h(h0, h1);
                ph[1] = pack2h(h2, h3);
                ph[2] = pack2h(h4, h5);
                ph[3] = pack2h(h6, h7);
                pl[0] = pack2h(__float2half_rn(pa[0] - __half2float(h0)),
                               __float2half_rn(pa[1] - __half2float(h1)));
                pl[1] = pack2h(__float2half_rn(pa[2] - __half2float(h2)),
                               __float2half_rn(pa[3] - __half2float(h3)));
                pl[2] = pack2h(__float2half_rn(pb[0] - __half2float(h4)),
                               __float2half_rn(pb[1] - __half2float(h5)));
                pl[3] = pack2h(__float2half_rn(pb[2] - __half2float(h6)),
                               __float2half_rn(pb[3] - __half2float(h7)));
            }
            uint32_t vh[4][4], vl[4][4];
#pragma unroll
            for (int jj = 0; jj < 4; ++jj) {
                uint32_t va = sb + SVHI + (kc * 16 + (lane & 15)) * VSTR +
                              (2 * jj + (lane >> 4)) * 16;
                ldm4t(vh[jj], va);
                ldm4t(vl[jj], va + (SVLO - SVHI));
            }
            // 3 term-major sweeps of 8 independent mmas
#pragma unroll
            for (int jj = 0; jj < 4; ++jj) {
                mma_f16(o[2 * jj], ph, vh[jj][0], vh[jj][1]);
                mma_f16(o[2 * jj + 1], ph, vh[jj][2], vh[jj][3]);
            }
#pragma unroll
            for (int jj = 0; jj < 4; ++jj) {
                mma_f16(o[2 * jj], ph, vl[jj][0], vl[jj][1]);
                mma_f16(o[2 * jj + 1], ph, vl[jj][2], vl[jj][3]);
            }
#pragma unroll
            for (int jj = 0; jj < 4; ++jj) {
                mma_f16(o[2 * jj], pl, vh[jj][0], vh[jj][1]);
                mma_f16(o[2 * jj + 1], pl, vh[jj][2], vh[jj][3]);
            }
        }
    }

    // ---- epilogue ----
    const float inv0 = 1.0f / l0, inv1 = 1.0f / l1;
    const size_t row0 = (size_t)(b * Nn + qn0) * Dd;
    const size_t row1 = (size_t)(b * Nn + qn1) * Dd;
#pragma unroll
    for (int nd = 0; nd < 8; ++nd) {
        const int col = h * 64 + nd * 8 + 2 * (lane & 3);
        *(float2*)(O + row0 + col) =
            make_float2(o[nd][0] * inv0, o[nd][1] * inv0);
        *(float2*)(O + row1 + col) =
            make_float2(o[nd][2] * inv1, o[nd][3] * inv1);
    }
}

// ---------------------------------------------------------------------------
// Launch
// ---------------------------------------------------------------------------
extern "C" void kernel_launch(void* const* d_in, const int* in_sizes, int n_in,
                              void* d_out, int out_size)
{
    const float* x  = (const float*)d_in[0];
    const int*   pd = (const int*)d_in[1];
    const float* wq = (const float*)d_in[2];
    const float* bq = (const float*)d_in[3];
    const float* wk = (const float*)d_in[4];
    const float* bk = (const float*)d_in[5];
    const float* wv = (const float*)d_in[6];
    const float* bv = (const float*)d_in[7];
    const float* wo = (const float*)d_in[8];
    const float* bo = (const float*)d_in[9];
    float* out = (float*)d_out;

    float *Q, *K, *V, *O, *WT;
    cudaGetSymbolAddress((void**)&Q, g_Q);
    cudaGetSymbolAddress((void**)&K, g_K);
    cudaGetSymbolAddress((void**)&V, g_V);
    cudaGetSymbolAddress((void**)&O, g_O);
    cudaGetSymbolAddress((void**)&WT, g_WT);

    cudaFuncSetAttribute(gemm_f16x3_kernel,
                         cudaFuncAttributeMaxDynamicSharedMemorySize, GEMM_SMEM);
    cudaFuncSetAttribute(attn_mma_kernel,
                         cudaFuncAttributeMaxDynamicSharedMemorySize, ATTN_SMEM);

    dim3 tgrid(32, 32), tblk(32, 8);
    transpose_k<<<tgrid, tblk>>>(wq, WT + 0 * 1024 * 1024);
    transpose_k<<<tgrid, tblk>>>(wk, WT + 1 * 1024 * 1024);
    transpose_k<<<tgrid, tblk>>>(wv, WT + 2 * 1024 * 1024);
    transpose_k<<<tgrid, tblk>>>(wo, WT + 3 * 1024 * 1024);

    dim3 ggrid(Dd / 128, Mm / 128); // (8, 64)
    gemm_f16x3_kernel<<<ggrid, 256, GEMM_SMEM>>>(x, WT + 0 * 1024 * 1024, bq, Q);
    gemm_f16x3_kernel<<<ggrid, 256, GEMM_SMEM>>>(x, WT + 1 * 1024 * 1024, bk, K);
    gemm_f16x3_kernel<<<ggrid, 256, GEMM_SMEM>>>(x, WT + 2 * 1024 * 1024, bv, V);

    dim3 agrid(Nn / 128, Bb * 16); // (16, 64)
    attn_mma_kernel<<<agrid, 256, ATTN_SMEM>>>(Q, K, V, pd, O);

    gemm_f16x3_kernel<<<ggrid, 256, GEMM_SMEM>>>(O, WT + 3 * 1024 * 1024, bo, out);
}